// round 5
// baseline (speedup 1.0000x reference)
#include <cuda_runtime.h>
#include <cuda_fp16.h>
#include <cstdint>

// Problem constants
#define BB 4096
#define OO 11008
#define KK 4096
#define GG 32               // K / group_size

// GEMM tiling
#define MT 128
#define NT 128
#define MTILES (BB / MT)    // 32
#define NTILES (OO / NT)    // 86
#define NCH 64              // 64-byte k-chunks
#define STAGE_BYTES 16384   // (128 A rows + 128 B rows) * 64 bytes

// plain row-major int8 scratch
__device__ __align__(1024) uint8_t g_xq[(size_t)BB * KK];  // 16.8 MB
__device__ __align__(1024) uint8_t g_wq[(size_t)OO * KK];  // 45 MB

// ---------------------------------------------------------------- helpers
__device__ __forceinline__ uint32_t smem_u32(const void* p) {
    uint32_t a;
    asm("{ .reg .u64 t; cvta.to.shared.u64 t, %1; cvt.u32.u64 %0, t; }" : "=r"(a) : "l"(p));
    return a;
}
__device__ __forceinline__ void cp16(uint32_t s, const void* g) {
    asm volatile("cp.async.cg.shared.global [%0], [%1], 16;" :: "r"(s), "l"(g));
}
__device__ __forceinline__ void cp_commit() {
    asm volatile("cp.async.commit_group;" ::: "memory");
}
__device__ __forceinline__ void cp_wait1() {
    asm volatile("cp.async.wait_group 1;" ::: "memory");
}
__device__ __forceinline__ void mma_s8(int* c, const uint32_t* a, const uint32_t* b) {
    asm volatile(
        "mma.sync.aligned.m16n8k32.row.col.s32.s8.s8.s32 "
        "{%0,%1,%2,%3}, {%4,%5,%6,%7}, {%8,%9}, {%0,%1,%2,%3};"
        : "+r"(c[0]), "+r"(c[1]), "+r"(c[2]), "+r"(c[3])
        : "r"(a[0]), "r"(a[1]), "r"(a[2]), "r"(a[3]), "r"(b[0]), "r"(b[1]));
}

// ---------------------------------------------------------------- prepack
// one thread -> one packed int32 (one byte = two nibbles, low first) -> two signed int8
__global__ void __launch_bounds__(256) prepack(const int* __restrict__ p,
                                               char2* __restrict__ outq, int total) {
    int i = blockIdx.x * blockDim.x + threadIdx.x;
    if (i >= total) return;
    int v = p[i];
    int lo = ((v & 15) ^ 8) - 8;
    int hi = (((v >> 4) & 15) ^ 8) - 8;
    outq[i] = make_char2((char)lo, (char)hi);
}

// ---------------------------------------------------------------- GEMM
// smem: 3 stages x (A 128 rows + B 128 rows) x 64 k-bytes.
// per row: four 16B chunks, chunk c stored at phys = c ^ ((row>>1)&3)
__global__ void __launch_bounds__(256, 1)
gemm_kernel(const float* __restrict__ a_scale, const float* __restrict__ w_scale,
            const float* __restrict__ bias, float* __restrict__ out) {
    __shared__ uint8_t s_data[3][STAGE_BYTES];   // 48 KB static, no opt-in needed

    int tid = threadIdx.x, wid = tid >> 5, lane = tid & 31;
    int g8 = lane >> 2, tig = lane & 3;
    int warp_m = (wid & 1) * 64;       // 2 warps in M (4 m16 tiles each)
    int warp_n = (wid >> 1) * 32;      // 4 warps in N (4 n8 tiles each)

    // supertile rasterization (8 m-tiles per group) for L2 reuse
    int bid = blockIdx.x;
    int grp = bid / (8 * NTILES);
    int rem = bid - grp * (8 * NTILES);
    int mt = grp * 8 + (rem & 7);
    int nt = rem >> 3;
    int m0 = mt * MT, n0 = nt * NT;

    const uint8_t* gA = g_xq + (size_t)m0 * KK;
    const uint8_t* gB = g_wq + (size_t)n0 * KK;

    // cp.async stage loader: 1024 x 16B per stage, 4 per thread
    // thread j (0..1023): tile = j>>9 (0=A,1=B), r = (j>>2)&127, c = j&3
    int ld_tile = tid >> 7;            // for j = tid:        0..1; pattern repeats with +256
    // we simply recompute inside the lambda-style macro below

#define LOAD_STAGE(slot, ch)                                                     \
    do {                                                                         \
        uint32_t st_ = smem_u32(&s_data[slot][0]);                               \
        const uint8_t* gk_ = 0;                                                  \
        _Pragma("unroll")                                                        \
        for (int it_ = 0; it_ < 4; it_++) {                                      \
            int j_ = tid + 256 * it_;                                            \
            int r_ = (j_ >> 2) & 127;                                            \
            int c_ = j_ & 3;                                                     \
            int phys_ = c_ ^ ((r_ >> 1) & 3);                                    \
            uint32_t sa_ = st_ + (uint32_t)((j_ >> 9) * 8192 + r_ * 64 + phys_ * 16); \
            gk_ = ((j_ >> 9) ? gB : gA) + (size_t)r_ * KK + (ch) * 64 + c_ * 16; \
            cp16(sa_, gk_);                                                      \
        }                                                                        \
    } while (0)

    // prologue: chunks 0,1
    LOAD_STAGE(0, 0);
    cp_commit();
    LOAD_STAGE(1, 1);
    cp_commit();

    float accf[4][4][4];
    #pragma unroll
    for (int a = 0; a < 4; a++)
        #pragma unroll
        for (int b = 0; b < 4; b++)
            #pragma unroll
            for (int c = 0; c < 4; c++) accf[a][b][c] = 0.f;

    for (int g = 0; g < GG; g++) {
        // per-group scales (float32 in memory)
        float rs[8], cs[8];
        #pragma unroll
        for (int m = 0; m < 4; m++) {
            int r = m0 + warp_m + m * 16 + g8;
            rs[2 * m]     = __ldg(a_scale + (size_t)r * GG + g);
            rs[2 * m + 1] = __ldg(a_scale + (size_t)(r + 8) * GG + g);
        }
        #pragma unroll
        for (int n = 0; n < 4; n++) {
            int c = n0 + warp_n + n * 8 + tig * 2;
            cs[2 * n]     = __ldg(w_scale + (size_t)c * GG + g);
            cs[2 * n + 1] = __ldg(w_scale + (size_t)(c + 1) * GG + g);
        }

        int accs[4][4][4];
        #pragma unroll
        for (int a = 0; a < 4; a++)
            #pragma unroll
            for (int b = 0; b < 4; b++)
                #pragma unroll
                for (int c = 0; c < 4; c++) accs[a][b][c] = 0;

        #pragma unroll
        for (int h = 0; h < 2; h++) {
            int ch = 2 * g + h;
            cp_wait1();
            __syncthreads();
            const uint8_t* stA = &s_data[ch % 3][0];
            const uint8_t* stB = stA + 8192;

            #pragma unroll
            for (int ks = 0; ks < 2; ks++) {
                uint32_t af[4][4];
                #pragma unroll
                for (int m = 0; m < 4; m++) {
                    int ra = warp_m + m * 16 + g8;          // rows ra and ra+8
                    int sw0 = (ra >> 1) & 3, sw8 = ((ra + 8) >> 1) & 3;
                    const uint8_t* p0 = stA + ra * 64 + tig * 4;
                    const uint8_t* p8 = stA + (ra + 8) * 64 + tig * 4;
                    af[m][0] = *(const uint32_t*)(p0 + (((2 * ks)     ^ sw0) << 4));
                    af[m][1] = *(const uint32_t*)(p8 + (((2 * ks)     ^ sw8) << 4));
                    af[m][2] = *(const uint32_t*)(p0 + (((2 * ks + 1) ^ sw0) << 4));
                    af[m][3] = *(const uint32_t*)(p8 + (((2 * ks + 1) ^ sw8) << 4));
                }
                uint32_t bf[4][2];
                #pragma unroll
                for (int n = 0; n < 4; n++) {
                    int rb = warp_n + n * 8 + g8;
                    int swb = (rb >> 1) & 3;
                    const uint8_t* pb = stB + rb * 64 + tig * 4;
                    bf[n][0] = *(const uint32_t*)(pb + (((2 * ks)     ^ swb) << 4));
                    bf[n][1] = *(const uint32_t*)(pb + (((2 * ks + 1) ^ swb) << 4));
                }
                #pragma unroll
                for (int m = 0; m < 4; m++)
                    #pragma unroll
                    for (int n = 0; n < 4; n++)
                        mma_s8(accs[m][n], af[m], bf[n]);
            }

            if (ch + 2 < NCH) {
                LOAD_STAGE((ch + 2) % 3, ch + 2);
            }
            cp_commit();   // commit (possibly empty) keeps group counting uniform
        }

        // exact group-wise dequant into f32 accumulators
        #pragma unroll
        for (int m = 0; m < 4; m++)
            #pragma unroll
            for (int n = 0; n < 4; n++) {
                accf[m][n][0] += (float)accs[m][n][0] * rs[2 * m]     * cs[2 * n];
                accf[m][n][1] += (float)accs[m][n][1] * rs[2 * m]     * cs[2 * n + 1];
                accf[m][n][2] += (float)accs[m][n][2] * rs[2 * m + 1] * cs[2 * n];
                accf[m][n][3] += (float)accs[m][n][3] * rs[2 * m + 1] * cs[2 * n + 1];
            }
    }

    // epilogue: emulate reference fp16 rounding exactly:
    // ref = fp16(sum) (+fp16) fp16(bias), stored upcast to float32
    #pragma unroll
    for (int m = 0; m < 4; m++)
        #pragma unroll
        for (int n = 0; n < 4; n++) {
            int row = m0 + warp_m + m * 16 + g8;
            int col = n0 + warp_n + n * 8 + tig * 2;
            __half hb0 = __float2half_rn(__ldg(bias + col));
            __half hb1 = __float2half_rn(__ldg(bias + col + 1));
            float2 lo, hi;
            lo.x = __half2float(__hadd(__float2half_rn(accf[m][n][0]), hb0));
            lo.y = __half2float(__hadd(__float2half_rn(accf[m][n][1]), hb1));
            hi.x = __half2float(__hadd(__float2half_rn(accf[m][n][2]), hb0));
            hi.y = __half2float(__hadd(__float2half_rn(accf[m][n][3]), hb1));
            *(float2*)(out + (size_t)row * OO + col) = lo;
            *(float2*)(out + (size_t)(row + 8) * OO + col) = hi;
        }
}

// ---------------------------------------------------------------- host
extern "C" void kernel_launch(void* const* d_in, const int* in_sizes, int n_in,
                              void* d_out, int out_size) {
    const int*   x        = (const int*)d_in[0];
    const float* a_scale  = (const float*)d_in[1];   // fp16 in reference -> float32 in harness
    const int*   w_packed = (const int*)d_in[2];
    const float* w_scale  = (const float*)d_in[3];
    const float* bias     = (const float*)d_in[4];
    float*       out      = (float*)d_out;

    void* xq = nullptr; void* wq = nullptr;
    cudaGetSymbolAddress(&xq, g_xq);
    cudaGetSymbolAddress(&wq, g_wq);

    int totx = BB * (KK / 2);
    int totw = OO * (KK / 2);
    prepack<<<(totx + 255) / 256, 256>>>(x, (char2*)xq, totx);
    prepack<<<(totw + 255) / 256, 256>>>(w_packed, (char2*)wq, totw);

    gemm_kernel<<<MTILES * NTILES, 256>>>(a_scale, w_scale, bias, out);
}

// round 6
// speedup vs baseline: 1.0304x; 1.0304x over previous
#include <cuda_runtime.h>
#include <cuda_fp16.h>
#include <cstdint>

// Problem constants
#define BB 4096
#define OO 11008
#define KK 4096
#define GG 32               // K / group_size (one group = 128 k = 128 bytes int8)

// GEMM tiling
#define MT 128
#define NT 128
#define MTILES (BB / MT)    // 32
#define NTILES (OO / NT)    // 86
#define STAGES 4
#define STAGE_BYTES 32768   // (128 A rows + 128 B rows) * 128 k-bytes
#define SCALE_BYTES 32768   // a-scales 16KB + w-scales 16KB (f32)
#define SMEM_TOTAL (SCALE_BYTES + STAGES * STAGE_BYTES)   // 163840

// plain row-major int8 scratch
__device__ __align__(1024) uint8_t g_xq[(size_t)BB * KK];  // 16.8 MB
__device__ __align__(1024) uint8_t g_wq[(size_t)OO * KK];  // 45 MB

// ---------------------------------------------------------------- helpers
__device__ __forceinline__ uint32_t smem_u32(const void* p) {
    uint32_t a;
    asm("{ .reg .u64 t; cvta.to.shared.u64 t, %1; cvt.u32.u64 %0, t; }" : "=r"(a) : "l"(p));
    return a;
}
__device__ __forceinline__ void cp16(uint32_t s, const void* g) {
    asm volatile("cp.async.cg.shared.global [%0], [%1], 16;" :: "r"(s), "l"(g));
}
__device__ __forceinline__ void cp_commit() {
    asm volatile("cp.async.commit_group;" ::: "memory");
}
__device__ __forceinline__ void cp_wait2() {
    asm volatile("cp.async.wait_group 2;" ::: "memory");
}
__device__ __forceinline__ void mma_s8(int* c, const uint32_t* a, const uint32_t* b) {
    asm volatile(
        "mma.sync.aligned.m16n8k32.row.col.s32.s8.s8.s32 "
        "{%0,%1,%2,%3}, {%4,%5,%6,%7}, {%8,%9}, {%0,%1,%2,%3};"
        : "+r"(c[0]), "+r"(c[1]), "+r"(c[2]), "+r"(c[3])
        : "r"(a[0]), "r"(a[1]), "r"(a[2]), "r"(a[3]), "r"(b[0]), "r"(b[1]));
}

// ---------------------------------------------------------------- prepack (fused)
// one thread -> one packed int32 -> two signed int8. Handles x then w by range.
#define TOTX (BB * KK / 2)
#define TOTW (OO * KK / 2)
__global__ void __launch_bounds__(256) prepack_all(const int* __restrict__ px,
                                                   const int* __restrict__ pw) {
    int i = blockIdx.x * blockDim.x + threadIdx.x;
    const int* src;
    char2* dst;
    int j;
    if (i < TOTX) { src = px; dst = (char2*)g_xq; j = i; }
    else if (i < TOTX + TOTW) { src = pw; dst = (char2*)g_wq; j = i - TOTX; }
    else return;
    int v = src[j];
    int lo = ((v & 15) ^ 8) - 8;
    int hi = (((v >> 4) & 15) ^ 8) - 8;
    dst[j] = make_char2((char)lo, (char)hi);
}

// ---------------------------------------------------------------- GEMM
// smem data: per stage, A rows 0..127 then B rows 0..127, each row 128 bytes.
// row layout: eight 16B chunks, chunk c stored at phys = c ^ (row & 7).
__global__ void __launch_bounds__(256, 1)
gemm_kernel(const float* __restrict__ a_scale, const float* __restrict__ w_scale,
            const float* __restrict__ bias, float* __restrict__ out) {
    extern __shared__ uint8_t smem[];
    float* s_as = (float*)smem;                    // [32 groups][128 rows]
    float* s_ws = (float*)(smem + 16384);          // [32 groups][128 cols]
    uint8_t* s_data = smem + SCALE_BYTES;

    int tid = threadIdx.x, wid = tid >> 5, lane = tid & 31;
    int g8 = lane >> 2, tig = lane & 3;
    int warp_m = (wid & 1) * 64;       // 2 warps in M (4 m16 tiles each)
    int warp_n = (wid >> 1) * 32;      // 4 warps in N (4 n8 tiles each)

    // supertile rasterization (8 m-tiles per group) for L2 reuse
    int bid = blockIdx.x;
    int grp = bid / (8 * NTILES);
    int rem = bid - grp * (8 * NTILES);
    int mt = grp * 8 + (rem & 7);
    int nt = rem >> 3;
    int m0 = mt * MT, n0 = nt * NT;

    // stage scales once per CTA, transposed to [group][row]
    #pragma unroll 4
    for (int i = tid; i < 4096; i += 256) {
        int g = i >> 7, r = i & 127;
        s_as[i] = __ldg(a_scale + (size_t)(m0 + r) * GG + g);
        s_ws[i] = __ldg(w_scale + (size_t)(n0 + r) * GG + g);
    }

    const uint8_t* gA = g_xq + (size_t)m0 * KK;
    const uint8_t* gB = g_wq + (size_t)n0 * KK;

    // stage loader: 2048 x 16B per stage, 8 cp16 per thread
    // j (0..2047): half = j>>10 (0=A,1=B), r = (j>>3)&127, c = j&7
#define LOAD_STAGE(slot, g_)                                                       \
    do {                                                                           \
        uint32_t st_ = smem_u32(s_data + (slot) * STAGE_BYTES);                    \
        _Pragma("unroll")                                                          \
        for (int it_ = 0; it_ < 8; it_++) {                                        \
            int j_ = tid + 256 * it_;                                              \
            int r_ = (j_ >> 3) & 127;                                              \
            int c_ = j_ & 7;                                                       \
            int phys_ = c_ ^ (r_ & 7);                                             \
            uint32_t sa_ = st_ + (uint32_t)((j_ >> 10) * 16384 + r_ * 128 + phys_ * 16); \
            const uint8_t* gp_ = ((j_ >> 10) ? gB : gA) + (size_t)r_ * KK + (g_) * 128 + c_ * 16; \
            cp16(sa_, gp_);                                                        \
        }                                                                          \
        cp_commit();                                                               \
    } while (0)

    // prologue: groups 0..2 into stages 0..2
    LOAD_STAGE(0, 0);
    LOAD_STAGE(1, 1);
    LOAD_STAGE(2, 2);

    float accf[4][4][4];
    #pragma unroll
    for (int a = 0; a < 4; a++)
        #pragma unroll
        for (int b = 0; b < 4; b++)
            #pragma unroll
            for (int c = 0; c < 4; c++) accf[a][b][c] = 0.f;

    for (int g = 0; g < GG; g++) {
        cp_wait2();            // stage g resident
        __syncthreads();       // also: all warps done computing on stage (g+3)&3's slot

        if (g + 3 < GG) LOAD_STAGE((g + 3) & 3, g + 3);

        const uint8_t* stA = s_data + (g & 3) * STAGE_BYTES;
        const uint8_t* stB = stA + 16384;

        int accs[4][4][4];
        #pragma unroll
        for (int a = 0; a < 4; a++)
            #pragma unroll
            for (int b = 0; b < 4; b++)
                #pragma unroll
                for (int c = 0; c < 4; c++) accs[a][b][c] = 0;

        // rows ra = warp_m + m*16 + g8 (+8): (ra & 7) == g8 for all m, likewise B.
        // so the swizzled in-row offset depends only on the k-chunk index.
        #pragma unroll
        for (int ks = 0; ks < 4; ks++) {
            int off0 = (((2 * ks)     ^ g8) << 4) + tig * 4;   // k = ks*32 + tig*4
            int off1 = (((2 * ks + 1) ^ g8) << 4) + tig * 4;   // k = ks*32 + 16 + tig*4
            uint32_t af[4][4];
            #pragma unroll
            for (int m = 0; m < 4; m++) {
                const uint8_t* p0 = stA + (warp_m + m * 16 + g8) * 128;
                af[m][0] = *(const uint32_t*)(p0 + off0);
                af[m][1] = *(const uint32_t*)(p0 + 1024 + off0);   // +8 rows
                af[m][2] = *(const uint32_t*)(p0 + off1);
                af[m][3] = *(const uint32_t*)(p0 + 1024 + off1);
            }
            uint32_t bf[4][2];
            #pragma unroll
            for (int n = 0; n < 4; n++) {
                const uint8_t* pb = stB + (warp_n + n * 8 + g8) * 128;
                bf[n][0] = *(const uint32_t*)(pb + off0);
                bf[n][1] = *(const uint32_t*)(pb + off1);
            }
            #pragma unroll
            for (int m = 0; m < 4; m++)
                #pragma unroll
                for (int n = 0; n < 4; n++)
                    mma_s8(accs[m][n], af[m], bf[n]);
        }

        // exact group-wise dequant into f32 accumulators (scales from smem)
        float rs[8], cs[8];
        #pragma unroll
        for (int m = 0; m < 4; m++) {
            int r = warp_m + m * 16 + g8;
            rs[2 * m]     = s_as[g * 128 + r];
            rs[2 * m + 1] = s_as[g * 128 + r + 8];
        }
        #pragma unroll
        for (int n = 0; n < 4; n++) {
            int c = warp_n + n * 8 + tig * 2;
            cs[2 * n]     = s_ws[g * 128 + c];
            cs[2 * n + 1] = s_ws[g * 128 + c + 1];
        }
        #pragma unroll
        for (int m = 0; m < 4; m++)
            #pragma unroll
            for (int n = 0; n < 4; n++) {
                accf[m][n][0] += (float)accs[m][n][0] * (rs[2 * m]     * cs[2 * n]);
                accf[m][n][1] += (float)accs[m][n][1] * (rs[2 * m]     * cs[2 * n + 1]);
                accf[m][n][2] += (float)accs[m][n][2] * (rs[2 * m + 1] * cs[2 * n]);
                accf[m][n][3] += (float)accs[m][n][3] * (rs[2 * m + 1] * cs[2 * n + 1]);
            }
    }

    // epilogue: emulate reference fp16 rounding, store upcast float32
    #pragma unroll
    for (int m = 0; m < 4; m++)
        #pragma unroll
        for (int n = 0; n < 4; n++) {
            int row = m0 + warp_m + m * 16 + g8;
            int col = n0 + warp_n + n * 8 + tig * 2;
            __half hb0 = __float2half_rn(__ldg(bias + col));
            __half hb1 = __float2half_rn(__ldg(bias + col + 1));
            float2 lo, hi;
            lo.x = __half2float(__hadd(__float2half_rn(accf[m][n][0]), hb0));
            lo.y = __half2float(__hadd(__float2half_rn(accf[m][n][1]), hb1));
            hi.x = __half2float(__hadd(__float2half_rn(accf[m][n][2]), hb0));
            hi.y = __half2float(__hadd(__float2half_rn(accf[m][n][3]), hb1));
            *(float2*)(out + (size_t)row * OO + col) = lo;
            *(float2*)(out + (size_t)(row + 8) * OO + col) = hi;
        }
}

// ---------------------------------------------------------------- host
extern "C" void kernel_launch(void* const* d_in, const int* in_sizes, int n_in,
                              void* d_out, int out_size) {
    const int*   x        = (const int*)d_in[0];
    const float* a_scale  = (const float*)d_in[1];   // fp16 in reference -> float32 in harness
    const int*   w_packed = (const int*)d_in[2];
    const float* w_scale  = (const float*)d_in[3];
    const float* bias     = (const float*)d_in[4];
    float*       out      = (float*)d_out;

    int tot = TOTX + TOTW;
    prepack_all<<<(tot + 255) / 256, 256>>>(x, w_packed);

    static bool attr_set = false;
    if (!attr_set) {
        cudaFuncSetAttribute(gemm_kernel, cudaFuncAttributeMaxDynamicSharedMemorySize, SMEM_TOTAL);
        attr_set = true;
    }
    gemm_kernel<<<MTILES * NTILES, 256, SMEM_TOTAL>>>(a_scale, w_scale, bias, out);
}